// round 14
// baseline (speedup 1.0000x reference)
#include <cuda_runtime.h>
#include <cuda_bf16.h>

// QuantumAttention: B=2, S=1024, EMBED=256, HEADS=64, DK=4.
// Pipeline: y = x@W^T (3x) -> quantum expvals (closed form, products of cosines)
// -> per-head attention (dk=4, S=1024) -> output (B,S,256).
//
// Quantum closed form: z_w = cos(p_w)*cos(ang_w + p_w)
//   E = ( z1*z2*z3, z0*z1, z0*z1*z2, z0*z1*z2*z3 )
//
// Attention softmax: |E|<=1 -> |score|<=2 -> exp in [0.14, 7.4], sum <= 7.6K.
// No running max needed => softmax numerator/denominator are PURE SUMS over
// keys => key-split parallel decomposition with additive combine.

typedef unsigned long long u64;

#define NB 2
#define NS 1024
#define NE 256
#define NH 64
#define NQ (NB * NH * NS)   // 131072 total queries

// Scratch: quantum expvals, layout [b][h][s][4]
__device__ float g_qe[NB * NH * NS * 4];
__device__ float g_ke[NB * NH * NS * 4];
__device__ float g_ve[NB * NH * NS * 4];
// Key-split partials: numerator float4 and denominator per (ksplit, query)
__device__ float4 g_pacc[2][NQ];
__device__ float  g_pden[2][NQ];

// ---------------- f32x2 packed helpers (sm_103a) ----------------
__device__ __forceinline__ u64 pk2(float lo, float hi) {
    u64 r; asm("mov.b64 %0, {%1, %2};" : "=l"(r) : "f"(lo), "f"(hi)); return r;
}
__device__ __forceinline__ void upk2(u64 v, float& lo, float& hi) {
    asm("mov.b64 {%0, %1}, %2;" : "=f"(lo), "=f"(hi) : "l"(v));
}
__device__ __forceinline__ u64 fma2_(u64 a, u64 b, u64 c) {
    u64 d; asm("fma.rn.f32x2 %0, %1, %2, %3;" : "=l"(d) : "l"(a), "l"(b), "l"(c)); return d;
}
__device__ __forceinline__ u64 mul2_(u64 a, u64 b) {
    u64 d; asm("mul.rn.f32x2 %0, %1, %2;" : "=l"(d) : "l"(a), "l"(b)); return d;
}
__device__ __forceinline__ u64 add2_(u64 a, u64 b) {
    u64 d; asm("add.rn.f32x2 %0, %1, %2;" : "=l"(d) : "l"(a), "l"(b)); return d;
}
__device__ __forceinline__ float ex2_(float x) {
    float r; asm("ex2.approx.ftz.f32 %0, %1;" : "=f"(r) : "f"(x)); return r;
}

// ---------------- Kernel A: QKV projection + quantum epilogue ----------------
// C(2048 x 768) = X(2048 x 256) @ [Wq;Wk;Wv]^T, tiled 64x64, BK=16,
// 256 threads, 4x4 microtile per thread. A-tile stored in smem PRE-DUPLICATED
// as f32x2 broadcast pairs (pk2(a,a)) and B-tile as f32x2 column pairs, so the
// inner loop is pure LDS.128 -> fma.rn.f32x2 with zero repack movs.
// Register double-buffered global loads. Each thread's 4 output columns are
// one aligned head group -> quantum transform in registers.
__global__ __launch_bounds__(256) void qkvq_kernel(
    const float* __restrict__ x,  const float* __restrict__ Wq,
    const float* __restrict__ Wk, const float* __restrict__ Wv,
    const float* __restrict__ params)
{
    __shared__ u64 Asd[16][64];   // Asd[k][r] = pk2(A[r][k], A[r][k])   (8 KB)
    __shared__ u64 BsP[16][32];   // BsP[k][c] = pk2(B[k][2c], B[k][2c+1]) (4 KB)

    const int tid = threadIdx.x;
    const int tx = tid & 15;
    const int ty = tid >> 4;
    const int bm = blockIdx.x;           // 0..31 : row tile (64 rows)
    const int gc0 = blockIdx.y * 64;     // 0..704: global output-col base

    const float* W;
    float* dst;
    if (gc0 < 256)      { W = Wq; dst = g_qe; }
    else if (gc0 < 512) { W = Wk; dst = g_ke; }
    else                { W = Wv; dst = g_ve; }
    const int nc0 = gc0 & 255;           // col base within this matrix

    // cooperative load indices: 64 rows x 16 cols per tile, float4 per thread
    const int lr = tid >> 2;             // 0..63
    const int lc = (tid & 3) << 2;       // 0,4,8,12
    const float* xrow = x + (bm * 64 + lr) * NE + lc;
    const float* wrow = W + (nc0 + lr) * NE + lc;

    u64 c01[4], c23[4];
#pragma unroll
    for (int i = 0; i < 4; i++) { c01[i] = 0ULL; c23[i] = 0ULL; }

    float4 av = *reinterpret_cast<const float4*>(xrow);
    float4 bv = *reinterpret_cast<const float4*>(wrow);

    for (int k0 = 0; k0 < NE; k0 += 16) {
        // A[r=lr][k=lc+j] -> duplicated pair
        Asd[lc + 0][lr] = pk2(av.x, av.x);
        Asd[lc + 1][lr] = pk2(av.y, av.y);
        Asd[lc + 2][lr] = pk2(av.z, av.z);
        Asd[lc + 3][lr] = pk2(av.w, av.w);
        // B[out-col=lr][k=lc+j] -> BsP[k][lr>>1] halves (two threads per pair)
        {
            float* bw = reinterpret_cast<float*>(&BsP[0][0]);
            const int base = lr;  // ((k)*32 + (lr>>1))*2 + (lr&1) == k*64 + lr
            bw[(lc + 0) * 64 + base] = bv.x;
            bw[(lc + 1) * 64 + base] = bv.y;
            bw[(lc + 2) * 64 + base] = bv.z;
            bw[(lc + 3) * 64 + base] = bv.w;
        }
        __syncthreads();
        if (k0 + 16 < NE) {
            av = *reinterpret_cast<const float4*>(xrow + k0 + 16);
            bv = *reinterpret_cast<const float4*>(wrow + k0 + 16);
        }
#pragma unroll
        for (int k = 0; k < 16; k++) {
            ulonglong2 ad01 = *reinterpret_cast<const ulonglong2*>(&Asd[k][ty * 4 + 0]);
            ulonglong2 ad23 = *reinterpret_cast<const ulonglong2*>(&Asd[k][ty * 4 + 2]);
            ulonglong2 bp   = *reinterpret_cast<const ulonglong2*>(&BsP[k][tx * 2]);
            c01[0] = fma2_(ad01.x, bp.x, c01[0]); c23[0] = fma2_(ad01.x, bp.y, c23[0]);
            c01[1] = fma2_(ad01.y, bp.x, c01[1]); c23[1] = fma2_(ad01.y, bp.y, c23[1]);
            c01[2] = fma2_(ad23.x, bp.x, c01[2]); c23[2] = fma2_(ad23.x, bp.y, c23[2]);
            c01[3] = fma2_(ad23.y, bp.x, c01[3]); c23[3] = fma2_(ad23.y, bp.y, c23[3]);
        }
        __syncthreads();
    }

    // quantum epilogue: each thread's 4 cols = one head's 4 angles
    const float p0 = params[0], p1 = params[1], p2 = params[2], p3 = params[3];
    const float cp0 = cosf(p0), cp1 = cosf(p1), cp2 = cosf(p2), cp3 = cosf(p3);
    const int h = (nc0 >> 2) + tx;       // head index 0..63

#pragma unroll
    for (int i = 0; i < 4; i++) {
        const int r = bm * 64 + ty * 4 + i;
        const int bb = r >> 10;
        const int s = r & 1023;
        float a0, a1, a2, a3;
        upk2(c01[i], a0, a1);
        upk2(c23[i], a2, a3);
        float z0 = cp0 * __cosf(a0 + p0);
        float z1 = cp1 * __cosf(a1 + p1);
        float z2 = cp2 * __cosf(a2 + p2);
        float z3 = cp3 * __cosf(a3 + p3);
        float e1 = z0 * z1;
        float e2 = e1 * z2;
        float e3 = e2 * z3;
        float e0 = (z1 * z2) * z3;
        reinterpret_cast<float4*>(dst)[(bb * NH + h) * NS + s] =
            make_float4(e0, e1, e2, e3);
    }
}

// ---------------- Kernel B: attention partials (key-split) ----------------
// Grid (128, 2, 2): block = (b,h) x query-half x key-half. 256 threads,
// 2 queries per thread, 256 key-pairs in smem pre-packed as f32x2 operand
// pairs. Writes partial numerator/denominator sums to scratch (additive
// softmax decomposition -- no max subtraction needed since |score| <= 2).
__global__ __launch_bounds__(256) void attn_part_kernel()
{
    __shared__ ulonglong2 KU[256];  // { pk(k0.x,k1.x), pk(k0.y,k1.y) }
    __shared__ ulonglong2 KW[256];  // { pk(k0.z,k1.z), pk(k0.w,k1.w) }
    __shared__ ulonglong2 VU[256];
    __shared__ ulonglong2 VW[256];

    const int bh = blockIdx.x;          // 0..127
    const int ks = blockIdx.z;          // key split 0/1
    const int tid = threadIdx.x;

    const float4* KE = reinterpret_cast<const float4*>(g_ke) + bh * NS + ks * 512;
    const float4* VE = reinterpret_cast<const float4*>(g_ve) + bh * NS + ks * 512;
    {
        const int pp = tid;             // 256 pairs, one per thread
        float4 k0 = KE[2 * pp], k1 = KE[2 * pp + 1];
        KU[pp] = make_ulonglong2(pk2(k0.x, k1.x), pk2(k0.y, k1.y));
        KW[pp] = make_ulonglong2(pk2(k0.z, k1.z), pk2(k0.w, k1.w));
        float4 v0 = VE[2 * pp], v1 = VE[2 * pp + 1];
        VU[pp] = make_ulonglong2(pk2(v0.x, v1.x), pk2(v0.y, v1.y));
        VW[pp] = make_ulonglong2(pk2(v0.z, v1.z), pk2(v0.w, v1.w));
    }
    __syncthreads();

    const float sc = 0.5f * 1.4426950408889634f;  // (1/sqrt(dk)) * log2(e)
    u64 q0[2], q1[2], q2[2], q3[2];
    u64 den[2], a0[2], a1[2], a2[2], a3[2];
#pragma unroll
    for (int qi = 0; qi < 2; qi++) {
        const int sq = blockIdx.y * 512 + qi * 256 + tid;
        float4 q = reinterpret_cast<const float4*>(g_qe)[bh * NS + sq];
        q0[qi] = pk2(q.x * sc, q.x * sc);
        q1[qi] = pk2(q.y * sc, q.y * sc);
        q2[qi] = pk2(q.z * sc, q.z * sc);
        q3[qi] = pk2(q.w * sc, q.w * sc);
        den[qi] = 0ULL;
        a0[qi] = 0ULL; a1[qi] = 0ULL; a2[qi] = 0ULL; a3[qi] = 0ULL;
    }

#pragma unroll 4
    for (int jj = 0; jj < 256; jj++) {
        const ulonglong2 ka = KU[jj];
        const ulonglong2 kb = KW[jj];
        const ulonglong2 va = VU[jj];
        const ulonglong2 vb = VW[jj];
#pragma unroll
        for (int qi = 0; qi < 2; qi++) {
            // 3-level score tree
            u64 sA = mul2_(q0[qi], ka.x);
            u64 sB = mul2_(q2[qi], kb.x);
            sA = fma2_(q1[qi], ka.y, sA);
            sB = fma2_(q3[qi], kb.y, sB);
            u64 s = add2_(sA, sB);
            float s0, s1; upk2(s, s0, s1);
            u64 e = pk2(ex2_(s0), ex2_(s1));
            den[qi] = add2_(den[qi], e);
            a0[qi] = fma2_(e, va.x, a0[qi]);
            a1[qi] = fma2_(e, va.y, a1[qi]);
            a2[qi] = fma2_(e, vb.x, a2[qi]);
            a3[qi] = fma2_(e, vb.y, a3[qi]);
        }
    }

#pragma unroll
    for (int qi = 0; qi < 2; qi++) {
        const int sq = blockIdx.y * 512 + qi * 256 + tid;
        const int qidx = bh * NS + sq;
        float dl, dh; upk2(den[qi], dl, dh);
        float l, hi_;
        upk2(a0[qi], l, hi_); float n0 = l + hi_;
        upk2(a1[qi], l, hi_); float n1 = l + hi_;
        upk2(a2[qi], l, hi_); float n2 = l + hi_;
        upk2(a3[qi], l, hi_); float n3 = l + hi_;
        g_pacc[ks][qidx] = make_float4(n0, n1, n2, n3);
        g_pden[ks][qidx] = dl + dh;
    }
}

// ---------------- Kernel C: combine key-split partials ----------------
__global__ __launch_bounds__(256) void attn_combine_kernel(float* __restrict__ out)
{
    const int idx = blockIdx.x * 256 + threadIdx.x;  // query index 0..NQ-1
    const int bh = idx >> 10;
    const int sq = idx & 1023;
    const int b = bh >> 6;
    const int h = bh & 63;

    float4 n0 = g_pacc[0][idx];
    float4 n1 = g_pacc[1][idx];
    const float inv = 1.0f / (g_pden[0][idx] + g_pden[1][idx]);
    reinterpret_cast<float4*>(out)[(b * NS + sq) * NH + h] =
        make_float4((n0.x + n1.x) * inv, (n0.y + n1.y) * inv,
                    (n0.z + n1.z) * inv, (n0.w + n1.w) * inv);
}

// ---------------- launch ----------------
extern "C" void kernel_launch(void* const* d_in, const int* in_sizes, int n_in,
                              void* d_out, int out_size) {
    const float* x      = (const float*)d_in[0];
    const float* Wq     = (const float*)d_in[1];
    const float* Wk     = (const float*)d_in[2];
    const float* Wv     = (const float*)d_in[3];
    const float* params = (const float*)d_in[4];
    float* out = (float*)d_out;

    qkvq_kernel<<<dim3(32, 12), 256>>>(x, Wq, Wk, Wv, params);
    attn_part_kernel<<<dim3(128, 2, 2), 256>>>();
    attn_combine_kernel<<<NQ / 256, 256>>>(out);
}

// round 16
// speedup vs baseline: 1.0146x; 1.0146x over previous
#include <cuda_runtime.h>
#include <cuda_bf16.h>

// QuantumAttention: B=2, S=1024, EMBED=256, HEADS=64, DK=4.
// Pipeline: y = x@W^T (3x) -> quantum expvals (closed form, products of cosines)
// -> per-head attention (dk=4, S=1024) -> output (B,S,256).
//
// Quantum closed form: z_w = cos(p_w)*cos(ang_w + p_w)
//   E = ( z1*z2*z3, z0*z1, z0*z1*z2, z0*z1*z2*z3 )
//
// Attention softmax: |E|<=1 -> |score|<=2 -> exp in [0.14, 7.4], sum <= 7.6K.
// No running max needed => softmax numerator/denominator are PURE SUMS over
// keys => key-split parallel decomposition with additive combine.

typedef unsigned long long u64;

#define NB 2
#define NS 1024
#define NE 256
#define NH 64
#define NQ (NB * NH * NS)   // 131072 total queries

// Scratch: quantum expvals, layout [b][h][s][4]
__device__ float g_qe[NB * NH * NS * 4];
__device__ float g_ke[NB * NH * NS * 4];
__device__ float g_ve[NB * NH * NS * 4];
// Key-split partials: numerator float4 and denominator per (ksplit, query)
__device__ float4 g_pacc[2][NQ];
__device__ float  g_pden[2][NQ];

// ---------------- f32x2 packed helpers (sm_103a) ----------------
__device__ __forceinline__ u64 pk2(float lo, float hi) {
    u64 r; asm("mov.b64 %0, {%1, %2};" : "=l"(r) : "f"(lo), "f"(hi)); return r;
}
__device__ __forceinline__ void upk2(u64 v, float& lo, float& hi) {
    asm("mov.b64 {%0, %1}, %2;" : "=f"(lo), "=f"(hi) : "l"(v));
}
__device__ __forceinline__ u64 fma2_(u64 a, u64 b, u64 c) {
    u64 d; asm("fma.rn.f32x2 %0, %1, %2, %3;" : "=l"(d) : "l"(a), "l"(b), "l"(c)); return d;
}
__device__ __forceinline__ u64 mul2_(u64 a, u64 b) {
    u64 d; asm("mul.rn.f32x2 %0, %1, %2;" : "=l"(d) : "l"(a), "l"(b)); return d;
}
__device__ __forceinline__ u64 add2_(u64 a, u64 b) {
    u64 d; asm("add.rn.f32x2 %0, %1, %2;" : "=l"(d) : "l"(a), "l"(b)); return d;
}
__device__ __forceinline__ float ex2_(float x) {
    float r; asm("ex2.approx.ftz.f32 %0, %1;" : "=f"(r) : "f"(x)); return r;
}

// ---------------- Kernel A: QKV projection + quantum epilogue ----------------
// C(2048 x 768) = X(2048 x 256) @ [Wq;Wk;Wv]^T, tiled 64x64, BK=16,
// 256 threads, 4x4 microtile per thread. A-tile stored in smem PRE-DUPLICATED
// as f32x2 broadcast pairs (pk2(a,a)) and B-tile as f32x2 column pairs, so the
// inner loop is pure LDS.128 -> fma.rn.f32x2 with zero repack movs.
// Register double-buffered global loads. Each thread's 4 output columns are
// one aligned head group -> quantum transform in registers.
__global__ __launch_bounds__(256) void qkvq_kernel(
    const float* __restrict__ x,  const float* __restrict__ Wq,
    const float* __restrict__ Wk, const float* __restrict__ Wv,
    const float* __restrict__ params)
{
    __shared__ u64 Asd[16][64];   // Asd[k][r] = pk2(A[r][k], A[r][k])   (8 KB)
    __shared__ u64 BsP[16][32];   // BsP[k][c] = pk2(B[k][2c], B[k][2c+1]) (4 KB)

    const int tid = threadIdx.x;
    const int tx = tid & 15;
    const int ty = tid >> 4;
    const int bm = blockIdx.x;           // 0..31 : row tile (64 rows)
    const int gc0 = blockIdx.y * 64;     // 0..704: global output-col base

    const float* W;
    float* dst;
    if (gc0 < 256)      { W = Wq; dst = g_qe; }
    else if (gc0 < 512) { W = Wk; dst = g_ke; }
    else                { W = Wv; dst = g_ve; }
    const int nc0 = gc0 & 255;           // col base within this matrix

    // cooperative load indices: 64 rows x 16 cols per tile, float4 per thread
    const int lr = tid >> 2;             // 0..63
    const int lc = (tid & 3) << 2;       // 0,4,8,12
    const float* xrow = x + (bm * 64 + lr) * NE + lc;
    const float* wrow = W + (nc0 + lr) * NE + lc;

    u64 c01[4], c23[4];
#pragma unroll
    for (int i = 0; i < 4; i++) { c01[i] = 0ULL; c23[i] = 0ULL; }

    float4 av = *reinterpret_cast<const float4*>(xrow);
    float4 bv = *reinterpret_cast<const float4*>(wrow);

    for (int k0 = 0; k0 < NE; k0 += 16) {
        // A[r=lr][k=lc+j] -> duplicated pair
        Asd[lc + 0][lr] = pk2(av.x, av.x);
        Asd[lc + 1][lr] = pk2(av.y, av.y);
        Asd[lc + 2][lr] = pk2(av.z, av.z);
        Asd[lc + 3][lr] = pk2(av.w, av.w);
        // B[out-col=lr][k=lc+j] -> BsP[k][lr>>1] halves (two threads per pair)
        {
            float* bw = reinterpret_cast<float*>(&BsP[0][0]);
            const int base = lr;  // ((k)*32 + (lr>>1))*2 + (lr&1) == k*64 + lr
            bw[(lc + 0) * 64 + base] = bv.x;
            bw[(lc + 1) * 64 + base] = bv.y;
            bw[(lc + 2) * 64 + base] = bv.z;
            bw[(lc + 3) * 64 + base] = bv.w;
        }
        __syncthreads();
        if (k0 + 16 < NE) {
            av = *reinterpret_cast<const float4*>(xrow + k0 + 16);
            bv = *reinterpret_cast<const float4*>(wrow + k0 + 16);
        }
#pragma unroll
        for (int k = 0; k < 16; k++) {
            ulonglong2 ad01 = *reinterpret_cast<const ulonglong2*>(&Asd[k][ty * 4 + 0]);
            ulonglong2 ad23 = *reinterpret_cast<const ulonglong2*>(&Asd[k][ty * 4 + 2]);
            ulonglong2 bp   = *reinterpret_cast<const ulonglong2*>(&BsP[k][tx * 2]);
            c01[0] = fma2_(ad01.x, bp.x, c01[0]); c23[0] = fma2_(ad01.x, bp.y, c23[0]);
            c01[1] = fma2_(ad01.y, bp.x, c01[1]); c23[1] = fma2_(ad01.y, bp.y, c23[1]);
            c01[2] = fma2_(ad23.x, bp.x, c01[2]); c23[2] = fma2_(ad23.x, bp.y, c23[2]);
            c01[3] = fma2_(ad23.y, bp.x, c01[3]); c23[3] = fma2_(ad23.y, bp.y, c23[3]);
        }
        __syncthreads();
    }

    // quantum epilogue: each thread's 4 cols = one head's 4 angles
    const float p0 = params[0], p1 = params[1], p2 = params[2], p3 = params[3];
    const float cp0 = cosf(p0), cp1 = cosf(p1), cp2 = cosf(p2), cp3 = cosf(p3);
    const int h = (nc0 >> 2) + tx;       // head index 0..63

#pragma unroll
    for (int i = 0; i < 4; i++) {
        const int r = bm * 64 + ty * 4 + i;
        const int bb = r >> 10;
        const int s = r & 1023;
        float a0, a1, a2, a3;
        upk2(c01[i], a0, a1);
        upk2(c23[i], a2, a3);
        float z0 = cp0 * __cosf(a0 + p0);
        float z1 = cp1 * __cosf(a1 + p1);
        float z2 = cp2 * __cosf(a2 + p2);
        float z3 = cp3 * __cosf(a3 + p3);
        float e1 = z0 * z1;
        float e2 = e1 * z2;
        float e3 = e2 * z3;
        float e0 = (z1 * z2) * z3;
        reinterpret_cast<float4*>(dst)[(bb * NH + h) * NS + s] =
            make_float4(e0, e1, e2, e3);
    }
}

// ---------------- Kernel B: attention partials (key-split) ----------------
// Grid (128, 2, 2): block = (b,h) x query-half x key-half. 256 threads,
// 2 queries per thread, 256 key-pairs in smem pre-packed as f32x2 operand
// pairs. Writes partial numerator/denominator sums to scratch (additive
// softmax decomposition -- no max subtraction needed since |score| <= 2).
__global__ __launch_bounds__(256) void attn_part_kernel()
{
    __shared__ ulonglong2 KU[256];  // { pk(k0.x,k1.x), pk(k0.y,k1.y) }
    __shared__ ulonglong2 KW[256];  // { pk(k0.z,k1.z), pk(k0.w,k1.w) }
    __shared__ ulonglong2 VU[256];
    __shared__ ulonglong2 VW[256];

    const int bh = blockIdx.x;          // 0..127
    const int ks = blockIdx.z;          // key split 0/1
    const int tid = threadIdx.x;

    const float4* KE = reinterpret_cast<const float4*>(g_ke) + bh * NS + ks * 512;
    const float4* VE = reinterpret_cast<const float4*>(g_ve) + bh * NS + ks * 512;
    {
        const int pp = tid;             // 256 pairs, one per thread
        float4 k0 = KE[2 * pp], k1 = KE[2 * pp + 1];
        KU[pp] = make_ulonglong2(pk2(k0.x, k1.x), pk2(k0.y, k1.y));
        KW[pp] = make_ulonglong2(pk2(k0.z, k1.z), pk2(k0.w, k1.w));
        float4 v0 = VE[2 * pp], v1 = VE[2 * pp + 1];
        VU[pp] = make_ulonglong2(pk2(v0.x, v1.x), pk2(v0.y, v1.y));
        VW[pp] = make_ulonglong2(pk2(v0.z, v1.z), pk2(v0.w, v1.w));
    }
    __syncthreads();

    const float sc = 0.5f * 1.4426950408889634f;  // (1/sqrt(dk)) * log2(e)
    u64 q0[2], q1[2], q2[2], q3[2];
    u64 den[2], a0[2], a1[2], a2[2], a3[2];
#pragma unroll
    for (int qi = 0; qi < 2; qi++) {
        const int sq = blockIdx.y * 512 + qi * 256 + tid;
        float4 q = reinterpret_cast<const float4*>(g_qe)[bh * NS + sq];
        q0[qi] = pk2(q.x * sc, q.x * sc);
        q1[qi] = pk2(q.y * sc, q.y * sc);
        q2[qi] = pk2(q.z * sc, q.z * sc);
        q3[qi] = pk2(q.w * sc, q.w * sc);
        den[qi] = 0ULL;
        a0[qi] = 0ULL; a1[qi] = 0ULL; a2[qi] = 0ULL; a3[qi] = 0ULL;
    }

#pragma unroll 4
    for (int jj = 0; jj < 256; jj++) {
        const ulonglong2 ka = KU[jj];
        const ulonglong2 kb = KW[jj];
        const ulonglong2 va = VU[jj];
        const ulonglong2 vb = VW[jj];
#pragma unroll
        for (int qi = 0; qi < 2; qi++) {
            // 3-level score tree
            u64 sA = mul2_(q0[qi], ka.x);
            u64 sB = mul2_(q2[qi], kb.x);
            sA = fma2_(q1[qi], ka.y, sA);
            sB = fma2_(q3[qi], kb.y, sB);
            u64 s = add2_(sA, sB);
            float s0, s1; upk2(s, s0, s1);
            u64 e = pk2(ex2_(s0), ex2_(s1));
            den[qi] = add2_(den[qi], e);
            a0[qi] = fma2_(e, va.x, a0[qi]);
            a1[qi] = fma2_(e, va.y, a1[qi]);
            a2[qi] = fma2_(e, vb.x, a2[qi]);
            a3[qi] = fma2_(e, vb.y, a3[qi]);
        }
    }

#pragma unroll
    for (int qi = 0; qi < 2; qi++) {
        const int sq = blockIdx.y * 512 + qi * 256 + tid;
        const int qidx = bh * NS + sq;
        float dl, dh; upk2(den[qi], dl, dh);
        float l, hi_;
        upk2(a0[qi], l, hi_); float n0 = l + hi_;
        upk2(a1[qi], l, hi_); float n1 = l + hi_;
        upk2(a2[qi], l, hi_); float n2 = l + hi_;
        upk2(a3[qi], l, hi_); float n3 = l + hi_;
        g_pacc[ks][qidx] = make_float4(n0, n1, n2, n3);
        g_pden[ks][qidx] = dl + dh;
    }
}

// ---------------- Kernel C: combine key-split partials ----------------
__global__ __launch_bounds__(256) void attn_combine_kernel(float* __restrict__ out)
{
    const int idx = blockIdx.x * 256 + threadIdx.x;  // query index 0..NQ-1
    const int bh = idx >> 10;
    const int sq = idx & 1023;
    const int b = bh >> 6;
    const int h = bh & 63;

    float4 n0 = g_pacc[0][idx];
    float4 n1 = g_pacc[1][idx];
    const float inv = 1.0f / (g_pden[0][idx] + g_pden[1][idx]);
    reinterpret_cast<float4*>(out)[(b * NS + sq) * NH + h] =
        make_float4((n0.x + n1.x) * inv, (n0.y + n1.y) * inv,
                    (n0.z + n1.z) * inv, (n0.w + n1.w) * inv);
}

// ---------------- launch ----------------
extern "C" void kernel_launch(void* const* d_in, const int* in_sizes, int n_in,
                              void* d_out, int out_size) {
    const float* x      = (const float*)d_in[0];
    const float* Wq     = (const float*)d_in[1];
    const float* Wk     = (const float*)d_in[2];
    const float* Wv     = (const float*)d_in[3];
    const float* params = (const float*)d_in[4];
    float* out = (float*)d_out;

    qkvq_kernel<<<dim3(32, 12), 256>>>(x, Wq, Wk, Wv, params);
    attn_part_kernel<<<dim3(128, 2, 2), 256>>>();
    attn_combine_kernel<<<NQ / 256, 256>>>(out);
}

// round 17
// speedup vs baseline: 1.0149x; 1.0003x over previous
#include <cuda_runtime.h>
#include <cuda_bf16.h>

// QuantumAttention: B=2, S=1024, EMBED=256, HEADS=64, DK=4.
// Pipeline: y = x@W^T (3x) -> quantum expvals (closed form, products of cosines)
// -> per-head attention (dk=4, S=1024) -> output (B,S,256).
//
// Quantum closed form: z_w = cos(p_w)*cos(ang_w + p_w)
//   E = ( z1*z2*z3, z0*z1, z0*z1*z2, z0*z1*z2*z3 )
//
// Attention softmax: |E|<=1 -> |score|<=2 -> exp in [0.14, 7.4], sum <= 7.6K.
// No running max needed => softmax numerator/denominator are PURE SUMS over
// keys => key-split parallel decomposition with additive combine.

typedef unsigned long long u64;

#define NB 2
#define NS 1024
#define NE 256
#define NH 64
#define NQ (NB * NH * NS)   // 131072 total queries

// Scratch: quantum expvals, layout [b][h][s][4]
__device__ float g_qe[NB * NH * NS * 4];
__device__ float g_ke[NB * NH * NS * 4];
__device__ float g_ve[NB * NH * NS * 4];
// Key-split partials: numerator float4 and denominator per (ksplit, query)
__device__ float4 g_pacc[2][NQ];
__device__ float  g_pden[2][NQ];

// ---------------- f32x2 packed helpers (sm_103a) ----------------
__device__ __forceinline__ u64 pk2(float lo, float hi) {
    u64 r; asm("mov.b64 %0, {%1, %2};" : "=l"(r) : "f"(lo), "f"(hi)); return r;
}
__device__ __forceinline__ void upk2(u64 v, float& lo, float& hi) {
    asm("mov.b64 {%0, %1}, %2;" : "=f"(lo), "=f"(hi) : "l"(v));
}
__device__ __forceinline__ u64 fma2_(u64 a, u64 b, u64 c) {
    u64 d; asm("fma.rn.f32x2 %0, %1, %2, %3;" : "=l"(d) : "l"(a), "l"(b), "l"(c)); return d;
}
__device__ __forceinline__ u64 mul2_(u64 a, u64 b) {
    u64 d; asm("mul.rn.f32x2 %0, %1, %2;" : "=l"(d) : "l"(a), "l"(b)); return d;
}
__device__ __forceinline__ u64 add2_(u64 a, u64 b) {
    u64 d; asm("add.rn.f32x2 %0, %1, %2;" : "=l"(d) : "l"(a), "l"(b)); return d;
}
__device__ __forceinline__ float ex2_(float x) {
    float r; asm("ex2.approx.ftz.f32 %0, %1;" : "=f"(r) : "f"(x)); return r;
}

// ---------------- Kernel A: QKV projection + quantum epilogue ----------------
// C(2048 x 768) = X(2048 x 256) @ [Wq;Wk;Wv]^T, tiled 64x64, BK=16,
// 256 threads, 4x4 microtile per thread. A-tile stored in smem PRE-DUPLICATED
// as f32x2 broadcast pairs (pk2(a,a)) and B-tile as f32x2 column pairs, so the
// inner loop is pure LDS.128 -> fma.rn.f32x2 with zero repack movs.
// Register double-buffered global loads. Each thread's 4 output columns are
// one aligned head group -> quantum transform in registers.
__global__ __launch_bounds__(256) void qkvq_kernel(
    const float* __restrict__ x,  const float* __restrict__ Wq,
    const float* __restrict__ Wk, const float* __restrict__ Wv,
    const float* __restrict__ params)
{
    __shared__ u64 Asd[16][64];   // Asd[k][r] = pk2(A[r][k], A[r][k])   (8 KB)
    __shared__ u64 BsP[16][32];   // BsP[k][c] = pk2(B[k][2c], B[k][2c+1]) (4 KB)

    const int tid = threadIdx.x;
    const int tx = tid & 15;
    const int ty = tid >> 4;
    const int bm = blockIdx.x;           // 0..31 : row tile (64 rows)
    const int gc0 = blockIdx.y * 64;     // 0..704: global output-col base

    const float* W;
    float* dst;
    if (gc0 < 256)      { W = Wq; dst = g_qe; }
    else if (gc0 < 512) { W = Wk; dst = g_ke; }
    else                { W = Wv; dst = g_ve; }
    const int nc0 = gc0 & 255;           // col base within this matrix

    // cooperative load indices: 64 rows x 16 cols per tile, float4 per thread
    const int lr = tid >> 2;             // 0..63
    const int lc = (tid & 3) << 2;       // 0,4,8,12
    const float* xrow = x + (bm * 64 + lr) * NE + lc;
    const float* wrow = W + (nc0 + lr) * NE + lc;

    u64 c01[4], c23[4];
#pragma unroll
    for (int i = 0; i < 4; i++) { c01[i] = 0ULL; c23[i] = 0ULL; }

    float4 av = *reinterpret_cast<const float4*>(xrow);
    float4 bv = *reinterpret_cast<const float4*>(wrow);

    for (int k0 = 0; k0 < NE; k0 += 16) {
        // A[r=lr][k=lc+j] -> duplicated pair
        Asd[lc + 0][lr] = pk2(av.x, av.x);
        Asd[lc + 1][lr] = pk2(av.y, av.y);
        Asd[lc + 2][lr] = pk2(av.z, av.z);
        Asd[lc + 3][lr] = pk2(av.w, av.w);
        // B[out-col=lr][k=lc+j] -> BsP[k][lr>>1] halves (two threads per pair)
        {
            float* bw = reinterpret_cast<float*>(&BsP[0][0]);
            const int base = lr;  // ((k)*32 + (lr>>1))*2 + (lr&1) == k*64 + lr
            bw[(lc + 0) * 64 + base] = bv.x;
            bw[(lc + 1) * 64 + base] = bv.y;
            bw[(lc + 2) * 64 + base] = bv.z;
            bw[(lc + 3) * 64 + base] = bv.w;
        }
        __syncthreads();
        if (k0 + 16 < NE) {
            av = *reinterpret_cast<const float4*>(xrow + k0 + 16);
            bv = *reinterpret_cast<const float4*>(wrow + k0 + 16);
        }
#pragma unroll
        for (int k = 0; k < 16; k++) {
            ulonglong2 ad01 = *reinterpret_cast<const ulonglong2*>(&Asd[k][ty * 4 + 0]);
            ulonglong2 ad23 = *reinterpret_cast<const ulonglong2*>(&Asd[k][ty * 4 + 2]);
            ulonglong2 bp   = *reinterpret_cast<const ulonglong2*>(&BsP[k][tx * 2]);
            c01[0] = fma2_(ad01.x, bp.x, c01[0]); c23[0] = fma2_(ad01.x, bp.y, c23[0]);
            c01[1] = fma2_(ad01.y, bp.x, c01[1]); c23[1] = fma2_(ad01.y, bp.y, c23[1]);
            c01[2] = fma2_(ad23.x, bp.x, c01[2]); c23[2] = fma2_(ad23.x, bp.y, c23[2]);
            c01[3] = fma2_(ad23.y, bp.x, c01[3]); c23[3] = fma2_(ad23.y, bp.y, c23[3]);
        }
        __syncthreads();
    }

    // quantum epilogue: each thread's 4 cols = one head's 4 angles
    const float p0 = params[0], p1 = params[1], p2 = params[2], p3 = params[3];
    const float cp0 = cosf(p0), cp1 = cosf(p1), cp2 = cosf(p2), cp3 = cosf(p3);
    const int h = (nc0 >> 2) + tx;       // head index 0..63

#pragma unroll
    for (int i = 0; i < 4; i++) {
        const int r = bm * 64 + ty * 4 + i;
        const int bb = r >> 10;
        const int s = r & 1023;
        float a0, a1, a2, a3;
        upk2(c01[i], a0, a1);
        upk2(c23[i], a2, a3);
        float z0 = cp0 * __cosf(a0 + p0);
        float z1 = cp1 * __cosf(a1 + p1);
        float z2 = cp2 * __cosf(a2 + p2);
        float z3 = cp3 * __cosf(a3 + p3);
        float e1 = z0 * z1;
        float e2 = e1 * z2;
        float e3 = e2 * z3;
        float e0 = (z1 * z2) * z3;
        reinterpret_cast<float4*>(dst)[(bb * NH + h) * NS + s] =
            make_float4(e0, e1, e2, e3);
    }
}

// ---------------- Kernel B: attention partials (key-split) ----------------
// Grid (128, 2, 2): block = (b,h) x query-half x key-half. 256 threads,
// 2 queries per thread, 256 key-pairs in smem pre-packed as f32x2 operand
// pairs. Writes partial numerator/denominator sums to scratch (additive
// softmax decomposition -- no max subtraction needed since |score| <= 2).
__global__ __launch_bounds__(256) void attn_part_kernel()
{
    __shared__ ulonglong2 KU[256];  // { pk(k0.x,k1.x), pk(k0.y,k1.y) }
    __shared__ ulonglong2 KW[256];  // { pk(k0.z,k1.z), pk(k0.w,k1.w) }
    __shared__ ulonglong2 VU[256];
    __shared__ ulonglong2 VW[256];

    const int bh = blockIdx.x;          // 0..127
    const int ks = blockIdx.z;          // key split 0/1
    const int tid = threadIdx.x;

    const float4* KE = reinterpret_cast<const float4*>(g_ke) + bh * NS + ks * 512;
    const float4* VE = reinterpret_cast<const float4*>(g_ve) + bh * NS + ks * 512;
    {
        const int pp = tid;             // 256 pairs, one per thread
        float4 k0 = KE[2 * pp], k1 = KE[2 * pp + 1];
        KU[pp] = make_ulonglong2(pk2(k0.x, k1.x), pk2(k0.y, k1.y));
        KW[pp] = make_ulonglong2(pk2(k0.z, k1.z), pk2(k0.w, k1.w));
        float4 v0 = VE[2 * pp], v1 = VE[2 * pp + 1];
        VU[pp] = make_ulonglong2(pk2(v0.x, v1.x), pk2(v0.y, v1.y));
        VW[pp] = make_ulonglong2(pk2(v0.z, v1.z), pk2(v0.w, v1.w));
    }
    __syncthreads();

    const float sc = 0.5f * 1.4426950408889634f;  // (1/sqrt(dk)) * log2(e)
    u64 q0[2], q1[2], q2[2], q3[2];
    u64 den[2], a0[2], a1[2], a2[2], a3[2];
#pragma unroll
    for (int qi = 0; qi < 2; qi++) {
        const int sq = blockIdx.y * 512 + qi * 256 + tid;
        float4 q = reinterpret_cast<const float4*>(g_qe)[bh * NS + sq];
        q0[qi] = pk2(q.x * sc, q.x * sc);
        q1[qi] = pk2(q.y * sc, q.y * sc);
        q2[qi] = pk2(q.z * sc, q.z * sc);
        q3[qi] = pk2(q.w * sc, q.w * sc);
        den[qi] = 0ULL;
        a0[qi] = 0ULL; a1[qi] = 0ULL; a2[qi] = 0ULL; a3[qi] = 0ULL;
    }

#pragma unroll 4
    for (int jj = 0; jj < 256; jj++) {
        const ulonglong2 ka = KU[jj];
        const ulonglong2 kb = KW[jj];
        const ulonglong2 va = VU[jj];
        const ulonglong2 vb = VW[jj];
#pragma unroll
        for (int qi = 0; qi < 2; qi++) {
            // 3-level score tree
            u64 sA = mul2_(q0[qi], ka.x);
            u64 sB = mul2_(q2[qi], kb.x);
            sA = fma2_(q1[qi], ka.y, sA);
            sB = fma2_(q3[qi], kb.y, sB);
            u64 s = add2_(sA, sB);
            float s0, s1; upk2(s, s0, s1);
            u64 e = pk2(ex2_(s0), ex2_(s1));
            den[qi] = add2_(den[qi], e);
            a0[qi] = fma2_(e, va.x, a0[qi]);
            a1[qi] = fma2_(e, va.y, a1[qi]);
            a2[qi] = fma2_(e, vb.x, a2[qi]);
            a3[qi] = fma2_(e, vb.y, a3[qi]);
        }
    }

#pragma unroll
    for (int qi = 0; qi < 2; qi++) {
        const int sq = blockIdx.y * 512 + qi * 256 + tid;
        const int qidx = bh * NS + sq;
        float dl, dh; upk2(den[qi], dl, dh);
        float l, hi_;
        upk2(a0[qi], l, hi_); float n0 = l + hi_;
        upk2(a1[qi], l, hi_); float n1 = l + hi_;
        upk2(a2[qi], l, hi_); float n2 = l + hi_;
        upk2(a3[qi], l, hi_); float n3 = l + hi_;
        g_pacc[ks][qidx] = make_float4(n0, n1, n2, n3);
        g_pden[ks][qidx] = dl + dh;
    }
}

// ---------------- Kernel C: combine key-split partials ----------------
__global__ __launch_bounds__(256) void attn_combine_kernel(float* __restrict__ out)
{
    const int idx = blockIdx.x * 256 + threadIdx.x;  // query index 0..NQ-1
    const int bh = idx >> 10;
    const int sq = idx & 1023;
    const int b = bh >> 6;
    const int h = bh & 63;

    float4 n0 = g_pacc[0][idx];
    float4 n1 = g_pacc[1][idx];
    const float inv = 1.0f / (g_pden[0][idx] + g_pden[1][idx]);
    reinterpret_cast<float4*>(out)[(b * NS + sq) * NH + h] =
        make_float4((n0.x + n1.x) * inv, (n0.y + n1.y) * inv,
                    (n0.z + n1.z) * inv, (n0.w + n1.w) * inv);
}

// ---------------- launch ----------------
extern "C" void kernel_launch(void* const* d_in, const int* in_sizes, int n_in,
                              void* d_out, int out_size) {
    const float* x      = (const float*)d_in[0];
    const float* Wq     = (const float*)d_in[1];
    const float* Wk     = (const float*)d_in[2];
    const float* Wv     = (const float*)d_in[3];
    const float* params = (const float*)d_in[4];
    float* out = (float*)d_out;

    qkvq_kernel<<<dim3(32, 12), 256>>>(x, Wq, Wk, Wv, params);
    attn_part_kernel<<<dim3(128, 2, 2), 256>>>();
    attn_combine_kernel<<<NQ / 256, 256>>>(out);
}